// round 15
// baseline (speedup 1.0000x reference)
#include <cuda_runtime.h>
#include <cuda_fp16.h>
#include <math.h>
#include <stdint.h>

#define KTOK 16384

// ---------------------------------------------------------------------------
// Scratch (__device__ globals per allocation rules)
// ---------------------------------------------------------------------------
__device__ __half g_Aph[(size_t)KTOK * 1536];        // [H | gamma] hi
__device__ __half g_Bp[(size_t)4096 * 1536];         // B'
__device__ __half g_W2h[512 * 1024];                 // W2 hi
__device__ __half g_W3th[(size_t)2048 * 4096];       // W3^T hi
__device__ __half g_W4th[(size_t)1024 * 2048];       // W4^T hi
__device__ float  g_b3part[16 * 2048];
__device__ float  g_bias3[2048];
__device__ __half g_U[(size_t)KTOK * 2048];          // U = A'@B'u
__device__ __half g_Vc[(size_t)KTOK * 2048];         // compacted V rows
__device__ int    g_flag[KTOK];
__device__ int    g_rows[KTOK];                      // compacted parent rows
__device__ int    g_inv[KTOK];                       // k -> compact position
__device__ int    g_count;

// ---------------------------------------------------------------------------
// PTX primitives (sm_80-era; compile under compute_103)
// ---------------------------------------------------------------------------
__device__ __forceinline__ uint32_t smem_u32(const void* p) {
    uint32_t a;
    asm("{ .reg .u64 t; cvta.to.shared.u64 t, %1; cvt.u32.u64 %0, t; }" : "=r"(a) : "l"(p));
    return a;
}
__device__ __forceinline__ void cp_async16(uint32_t dst, const void* src) {
    asm volatile("cp.async.cg.shared.global [%0], [%1], 16;" :: "r"(dst), "l"(src));
}
#define CP_COMMIT() asm volatile("cp.async.commit_group;" ::: "memory")
#define CP_WAIT(n)  asm volatile("cp.async.wait_group %0;" :: "n"(n) : "memory")

__device__ __forceinline__ void ldsm_x4(uint32_t* r, uint32_t addr) {
    asm volatile("ldmatrix.sync.aligned.m8n8.x4.shared.b16 {%0,%1,%2,%3}, [%4];"
                 : "=r"(r[0]), "=r"(r[1]), "=r"(r[2]), "=r"(r[3]) : "r"(addr));
}
__device__ __forceinline__ void mma16816(float* d, const uint32_t* a,
                                         uint32_t b0, uint32_t b1) {
    asm volatile("mma.sync.aligned.m16n8k16.row.col.f32.f16.f16.f32 "
                 "{%0,%1,%2,%3}, {%4,%5,%6,%7}, {%8,%9}, {%0,%1,%2,%3};"
                 : "+f"(d[0]), "+f"(d[1]), "+f"(d[2]), "+f"(d[3])
                 : "r"(a[0]), "r"(a[1]), "r"(a[2]), "r"(a[3]), "r"(b0), "r"(b1));
}

// ---------------------------------------------------------------------------
// Parent-row compaction: zero -> mark -> single-block scan (deterministic)
// ---------------------------------------------------------------------------
__global__ void zero_flags_kernel() {
    int i = blockIdx.x * blockDim.x + threadIdx.x;   // KTOK threads
    g_flag[i] = 0;
    g_rows[i] = 0;
}
__global__ void mark_kernel(const int* __restrict__ parent) {
    int i = blockIdx.x * blockDim.x + threadIdx.x;
    g_flag[parent[i]] = 1;
}
__global__ void scan_kernel() {
    __shared__ int sc[512];
    int t = threadIdx.x;
    int base = t * 32;
    int cnt = 0;
#pragma unroll
    for (int i = 0; i < 32; i++) cnt += g_flag[base + i];
    sc[t] = cnt;
    __syncthreads();
    for (int off = 1; off < 512; off <<= 1) {
        int v = sc[t];
        int add = (t >= off) ? sc[t - off] : 0;
        __syncthreads();
        sc[t] = v + add;
        __syncthreads();
    }
    int pos = sc[t] - cnt;   // exclusive prefix
    if (t == 511) g_count = sc[511];
#pragma unroll
    for (int i = 0; i < 32; i++) {
        int k = base + i;
        if (g_flag[k]) {
            g_rows[pos] = k;
            g_inv[k] = pos;
            pos++;
        }
    }
}

// ---------------------------------------------------------------------------
// Activations, one block per row r
// ---------------------------------------------------------------------------
__global__ void act_kernel(const float* __restrict__ pos,
                           const float* __restrict__ W1,
                           const float* __restrict__ b1) {
    int r = blockIdx.x;
    int t = threadIdx.x;
    float p0 = pos[r * 3 + 0];
    float p1 = pos[r * 3 + 1];
    float p2 = pos[r * 3 + 2];
    __half* rowp = g_Aph + (size_t)r * 1536;
#pragma unroll
    for (int j = t; j < 512; j += 256) {
        float a = b1[j];
        a = fmaf(p0, W1[j], a);
        a = fmaf(p1, W1[512 + j], a);
        a = fmaf(p2, W1[1024 + j], a);
        rowp[j] = __float2half_rn(fmaxf(a, 0.0f));
    }
#pragma unroll
    for (int i = t; i < 512; i += 256) {
        float inv = exp2f(-(float)i * (13.287712379549449f / 512.0f));
        float s, c;
        sincosf((float)r * inv, &s, &c);
        *(__half2*)(rowp + 512 + 2 * i) =
            __halves2half2(__float2half_rn(s), __float2half_rn(c));
    }
}

// ---------------------------------------------------------------------------
// W3 transpose (hi only) fused with B' gamma-column scatter
// ---------------------------------------------------------------------------
__global__ void transpose_w3_kernel(const float* __restrict__ in) {
    __shared__ float tile[32][33];
    int c = blockIdx.x * 32 + threadIdx.x;
    int r0 = blockIdx.y * 32;
#pragma unroll
    for (int k = 0; k < 32; k += 8)
        tile[threadIdx.y + k][threadIdx.x] = in[(size_t)(r0 + threadIdx.y + k) * 2048 + c];
    __syncthreads();
    int m0 = blockIdx.x * 32;
    int j = r0 + threadIdx.x;
#pragma unroll
    for (int k = 0; k < 32; k += 8) {
        int m = m0 + threadIdx.y + k;
        __half h = __float2half_rn(tile[threadIdx.x][threadIdx.y + k]);
        g_W3th[(size_t)m * 4096 + j] = h;
        if (j >= 1024 && j < 2048)
            g_Bp[(size_t)m * 1536 + 512 + (j - 1024)] = h;
        else if (j >= 3072)
            g_Bp[(size_t)(2048 + m) * 1536 + 512 + (j - 3072)] = h;
    }
}

// generic transpose (hi only): in fp32 [R,C] -> out fp16 [C,R]
__global__ void transpose_hi_kernel(const float* __restrict__ in,
                                    __half* __restrict__ oh, int R, int C) {
    __shared__ float tile[32][33];
    int c = blockIdx.x * 32 + threadIdx.x;
    int r0 = blockIdx.y * 32;
#pragma unroll
    for (int k = 0; k < 32; k += 8)
        tile[threadIdx.y + k][threadIdx.x] = in[(size_t)(r0 + threadIdx.y + k) * C + c];
    __syncthreads();
    int orow0 = blockIdx.x * 32;
    int ocol = r0 + threadIdx.x;
#pragma unroll
    for (int k = 0; k < 32; k += 8)
        oh[(size_t)(orow0 + threadIdx.y + k) * R + ocol] =
            __float2half_rn(tile[threadIdx.x][threadIdx.y + k]);
}

__global__ void split_w2_kernel(const float* __restrict__ W2) {
    int idx = blockIdx.x * blockDim.x + threadIdx.x;
    g_W2h[idx] = __float2half_rn(W2[idx]);
}

// bias3 two-phase deterministic reduction
__global__ void bias3_part_kernel(const float* __restrict__ W3,
                                  const float* __restrict__ b2) {
    int m = blockIdx.x * blockDim.x + threadIdx.x;
    int j0 = blockIdx.y * 64;
    float s = 0.0f;
#pragma unroll 8
    for (int j = j0; j < j0 + 64; j++)
        s += b2[j] * (W3[(size_t)j * 2048 + m] + W3[(size_t)(2048 + j) * 2048 + m]);
    g_b3part[blockIdx.y * 2048 + m] = s;
}
__global__ void bias3_reduce_kernel(const float* __restrict__ b3) {
    int m = blockIdx.x * blockDim.x + threadIdx.x;
    float s = b3[m];
#pragma unroll
    for (int c = 0; c < 16; c++) s += g_b3part[c * 2048 + m];
    g_bias3[m] = s;
}

// ---------------------------------------------------------------------------
// HMMA GEMM: C[M,N] = A[M,Kd] @ Bt[N,Kd]^T, 1-pass fp16, OUT fp16.
// BM=128, BN=256, BK=64; 512 threads, 16 warps (4x4), warp tile 32x64;
// 4-stage cp.async, single barrier/chunk.
// MODE 1: SPLITROW (prep GEMM).
// MODE 3: merged U+V. grid.y in [0,128) = V part (gathered rows, early exit
//   past g_count, B = Bv, C = Vc); grid.y in [128,256) = U part.
// ---------------------------------------------------------------------------
#define BM 128
#define BN 256
#define BKK 64
#define NTHREADS 512
#define A_TILE 16384
#define B_TILE 32768
#define STAGE_BYTES (A_TILE + B_TILE)
#define DYN_SMEM (4 * STAGE_BYTES)

__device__ __forceinline__ uint32_t sw_off(int row, int ch) {
    return (uint32_t)(row * 128 + ((ch ^ (row & 7)) << 4));
}
template <int ROWS>
__device__ __forceinline__ void load_tile(uint32_t sbase, const __half* g,
                                          int ldk, int tid) {
#pragma unroll
    for (int i = 0; i < ROWS * 8 / NTHREADS; i++) {
        int id = tid + i * NTHREADS;
        int row = id >> 3, ch = id & 7;
        cp_async16(sbase + sw_off(row, ch), g + (size_t)row * ldk + ch * 8);
    }
}

template <int MODE>
__global__ __launch_bounds__(NTHREADS, 1) void hmma_gemm_kernel(
    const __half* __restrict__ Ah, const __half* __restrict__ Bh,
    __half* __restrict__ Ch, __half* __restrict__ Ch2,
    int Kd, int ldA, int ldB, int ldC) {
    __shared__ int srow[BM];
    extern __shared__ char smem[];
    const uint32_t sbase = smem_u32(smem);

    const int tid = threadIdx.x;
    const int wid = tid >> 5;
    const int lane = tid & 31;
    const int wm = wid >> 2;          // 0..3 (32-row slice)
    const int wn = wid & 3;           // 0..3 (64-col slice)

    const size_t n0 = (size_t)blockIdx.x * BN;
    const int NC = Kd / BKK;

    bool vpart = false;
    size_t m0;
    const __half* gAh;
    const __half* gBh;
    __half* Cout;
    if (MODE == 3) {
        vpart = blockIdx.y < 128;
        if (vpart) {
            m0 = (size_t)blockIdx.y * BM;
            if ((int)m0 >= g_count) return;
            if (tid < BM) srow[tid] = g_rows[m0 + tid];
            __syncthreads();
            gAh = Ah;                                 // gathered via srow
            gBh = Bh + (size_t)2048 * ldB + n0 * ldB; // B'v
            Cout = Ch2;                               // Vc
        } else {
            m0 = (size_t)(blockIdx.y - 128) * BM;
            gAh = Ah + m0 * ldA;
            gBh = Bh + n0 * ldB;                      // B'u
            Cout = Ch;                                // U
        }
    } else {   // MODE 1: SPLITROW prep
        m0 = (size_t)blockIdx.y * BM;
        gAh = (m0 >= 2048) ? (Ah + (m0 - 2048) * ldA + 2048) : (Ah + m0 * ldA);
        gBh = Bh + n0 * ldB;
        Cout = Ch;
    }

    auto load_a = [&](uint32_t sb, int k0) {
#pragma unroll
        for (int i = 0; i < BM * 8 / NTHREADS; i++) {   // 2
            int id = tid + i * NTHREADS;
            int row = id >> 3, ch = id & 7;
            const __half* src = (MODE == 3 && vpart)
                ? gAh + (size_t)srow[row] * ldA + k0 + ch * 8
                : gAh + (size_t)row * ldA + k0 + ch * 8;
            cp_async16(sb + sw_off(row, ch), src);
        }
    };

#pragma unroll
    for (int s = 0; s < 3; s++) {
        uint32_t sb = sbase + s * STAGE_BYTES;
        int k0 = s * BKK;
        load_a(sb, k0);
        load_tile<256>(sb + A_TILE, gBh + k0, ldB, tid);
        CP_COMMIT();
    }

    float acc[2][8][4];
#pragma unroll
    for (int mi = 0; mi < 2; mi++)
#pragma unroll
        for (int ni = 0; ni < 8; ni++)
#pragma unroll
            for (int q = 0; q < 4; q++) acc[mi][ni][q] = 0.0f;

    const int a_row = wm * 32 + (lane & 15);
    const int b_row = wn * 64 + (lane & 15);
    const int kc_lane = lane >> 4;

    for (int c = 0; c < NC; c++) {
        CP_WAIT(2);
        __syncthreads();   // protects stage (c-1)&3 (prefetch target) too

        int pf = c + 3;
        if (pf < NC) {
            uint32_t sb = sbase + (pf & 3) * STAGE_BYTES;
            int k0 = pf * BKK;
            load_a(sb, k0);
            load_tile<256>(sb + A_TILE, gBh + k0, ldB, tid);
        }
        CP_COMMIT();

        uint32_t sA = sbase + (c & 3) * STAGE_BYTES;
        uint32_t sB = sA + A_TILE;

#pragma unroll
        for (int ks = 0; ks < 4; ks++) {
            int kc = ks * 2 + kc_lane;
            uint32_t b_h[4][4];
#pragma unroll
            for (int j = 0; j < 4; j++)
                ldsm_x4(b_h[j], sB + sw_off(b_row + j * 16, kc));
#pragma unroll
            for (int mi = 0; mi < 2; mi++) {
                uint32_t a_h[4];
                ldsm_x4(a_h, sA + sw_off(a_row + mi * 16, kc));
#pragma unroll
                for (int ni = 0; ni < 8; ni++) {
                    int j = ni >> 1, s = ni & 1;
                    mma16816(acc[mi][ni], a_h, b_h[j][s], b_h[j][s + 2]);
                }
            }
        }
    }

    const int tm = lane >> 2;
    const int tn = lane & 3;
#pragma unroll
    for (int mi = 0; mi < 2; mi++) {
#pragma unroll
        for (int h = 0; h < 2; h++) {
            size_t row = m0 + wm * 32 + mi * 16 + h * 8 + tm;
#pragma unroll
            for (int ni = 0; ni < 8; ni++) {
                size_t col = n0 + wn * 64 + ni * 8 + tn * 2;
                *(__half2*)(Cout + row * ldC + col) =
                    __halves2half2(__float2half_rn(acc[mi][ni][h * 2 + 0]),
                                   __float2half_rn(acc[mi][ni][h * 2 + 1]));
            }
        }
    }
}

// ---------------------------------------------------------------------------
// Fused final GEMM: out[K,1024] = relu(U[k] + Vc[inv[par[k]]] + bias3) @ W4t^T + b4
// 512 threads, warp grid 4x4, warp tile 32x64; 3 stages.
// ---------------------------------------------------------------------------
#define F_STAGE (2 * A_TILE + B_TILE)
#define F_TILES_OFF 4608   // 512B parent + 4KB bias, 128B-aligned
#define F_DYN (F_TILES_OFF + 3 * F_STAGE)

__global__ __launch_bounds__(NTHREADS, 1) void fused_final_kernel(
    const __half* __restrict__ U, const __half* __restrict__ Vc,
    const __half* __restrict__ W4t,
    const int* __restrict__ parent, const float* __restrict__ bias3,
    const float* __restrict__ b4, float* __restrict__ out) {
    extern __shared__ char smem[];
    int* spar = (int*)smem;
    __half2* sbias = (__half2*)(smem + 512);
    const uint32_t tbase = smem_u32(smem) + F_TILES_OFF;

    const int tid = threadIdx.x;
    const int wid = tid >> 5;
    const int lane = tid & 31;
    const int wm = wid >> 2;
    const int wn = wid & 3;

    const size_t m0 = (size_t)blockIdx.y * BM;
    const size_t n0 = (size_t)blockIdx.x * BN;
    const int NC = 2048 / BKK;   // 32

    if (tid < 128) spar[tid] = g_inv[parent[m0 + tid]];
#pragma unroll
    for (int i = tid; i < 1024; i += NTHREADS)
        sbias[i] = __halves2half2(__float2half_rn(bias3[2 * i]),
                                  __float2half_rn(bias3[2 * i + 1]));
    __syncthreads();

    const __half* gU = U + m0 * 2048;
    const __half* gB = W4t + n0 * 2048;

    auto load_stage = [&](int stage, int k0) {
        uint32_t sb = tbase + stage * F_STAGE;
#pragma unroll
        for (int i = 0; i < 2; i++) {
            int id = tid + i * NTHREADS;
            int row = id >> 3, ch = id & 7;
            cp_async16(sb + sw_off(row, ch), gU + (size_t)row * 2048 + k0 + ch * 8);
        }
#pragma unroll
        for (int i = 0; i < 2; i++) {
            int id = tid + i * NTHREADS;
            int row = id >> 3, ch = id & 7;
            cp_async16(sb + A_TILE + sw_off(row, ch),
                       Vc + (size_t)spar[row] * 2048 + k0 + ch * 8);
        }
#pragma unroll
        for (int i = 0; i < 4; i++) {
            int id = tid + i * NTHREADS;
            int row = id >> 3, ch = id & 7;
            cp_async16(sb + 2 * A_TILE + sw_off(row, ch), gB + (size_t)row * 2048 + k0 + ch * 8);
        }
        CP_COMMIT();
    };

    load_stage(0, 0);
    load_stage(1, BKK);

    float acc[2][8][4];
#pragma unroll
    for (int mi = 0; mi < 2; mi++)
#pragma unroll
        for (int ni = 0; ni < 8; ni++)
#pragma unroll
            for (int q = 0; q < 4; q++) acc[mi][ni][q] = 0.0f;

    const int a_row = wm * 32 + (lane & 15);
    const int b_row = wn * 64 + (lane & 15);
    const int kc_lane = lane >> 4;
    const __half2 zero2 = __float2half2_rn(0.0f);

    for (int c = 0; c < NC; c++) {
        CP_WAIT(1);
        __syncthreads();   // single barrier per chunk

        if (c + 2 < NC) load_stage((c + 2) % 3, (c + 2) * BKK);
        else CP_COMMIT();

        uint32_t sU = tbase + (c % 3) * F_STAGE;
        uint32_t sV = sU + A_TILE;
        uint32_t sB = sU + 2 * A_TILE;

#pragma unroll
        for (int ks = 0; ks < 4; ks++) {
            int kc = ks * 2 + kc_lane;
            __half2 b_lo = sbias[c * 32 + ks * 8 + (lane & 3)];
            __half2 b_hi = sbias[c * 32 + ks * 8 + 4 + (lane & 3)];

            uint32_t b_h[4][4];
#pragma unroll
            for (int j = 0; j < 4; j++)
                ldsm_x4(b_h[j], sB + sw_off(b_row + j * 16, kc));
#pragma unroll
            for (int mi = 0; mi < 2; mi++) {
                uint32_t u[4], v[4], a_h[4];
                uint32_t off = sw_off(a_row + mi * 16, kc);
                ldsm_x4(u, sU + off);
                ldsm_x4(v, sV + off);
#pragma unroll
                for (int q = 0; q < 4; q++) {
                    __half2 s = __hadd2(*(__half2*)&u[q], *(__half2*)&v[q]);
                    s = __hadd2(s, (q < 2) ? b_lo : b_hi);
                    s = __hmax2(s, zero2);
                    a_h[q] = *(uint32_t*)&s;
                }
#pragma unroll
                for (int ni = 0; ni < 8; ni++) {
                    int j = ni >> 1, s = ni & 1;
                    mma16816(acc[mi][ni], a_h, b_h[j][s], b_h[j][s + 2]);
                }
            }
        }
    }

    const int tm = lane >> 2;
    const int tn = lane & 3;
#pragma unroll
    for (int mi = 0; mi < 2; mi++) {
#pragma unroll
        for (int h = 0; h < 2; h++) {
            size_t row = m0 + wm * 32 + mi * 16 + h * 8 + tm;
#pragma unroll
            for (int ni = 0; ni < 8; ni++) {
                size_t col = n0 + wn * 64 + ni * 8 + tn * 2;
                float2 bv = *(const float2*)(b4 + col);
                *(float2*)(out + row * 1024 + col) =
                    make_float2(acc[mi][ni][h * 2 + 0] + bv.x,
                                acc[mi][ni][h * 2 + 1] + bv.y);
            }
        }
    }
}

// ---------------------------------------------------------------------------
// Launch: fork-join two-stream graph.
// ---------------------------------------------------------------------------
extern "C" void kernel_launch(void* const* d_in, const int* in_sizes, int n_in,
                              void* d_out, int out_size) {
    const float* positions = (const float*)d_in[0];
    const int*   parent    = (const int*)d_in[1];
    const float* W1 = (const float*)d_in[2];
    const float* b1 = (const float*)d_in[3];
    const float* W2 = (const float*)d_in[4];
    const float* b2 = (const float*)d_in[5];
    const float* W3 = (const float*)d_in[6];
    const float* b3 = (const float*)d_in[7];
    const float* W4 = (const float*)d_in[8];
    const float* b4 = (const float*)d_in[9];
    float* out = (float*)d_out;

    __half *dAph, *dBp, *dW2h, *dW3th, *dW4th, *dU, *dVc;
    cudaGetSymbolAddress((void**)&dAph, g_Aph);
    cudaGetSymbolAddress((void**)&dBp, g_Bp);
    cudaGetSymbolAddress((void**)&dW2h, g_W2h);
    cudaGetSymbolAddress((void**)&dW3th, g_W3th);
    cudaGetSymbolAddress((void**)&dW4th, g_W4th);
    cudaGetSymbolAddress((void**)&dU, g_U);
    cudaGetSymbolAddress((void**)&dVc, g_Vc);
    float* dbias3;
    cudaGetSymbolAddress((void**)&dbias3, g_bias3);

    cudaFuncSetAttribute(hmma_gemm_kernel<1>,
                         cudaFuncAttributeMaxDynamicSharedMemorySize, DYN_SMEM);
    cudaFuncSetAttribute(hmma_gemm_kernel<3>,
                         cudaFuncAttributeMaxDynamicSharedMemorySize, DYN_SMEM);
    cudaFuncSetAttribute(fused_final_kernel,
                         cudaFuncAttributeMaxDynamicSharedMemorySize, F_DYN);

    // persistent side-stream + events (host handles only; same GPU work each call)
    static cudaStream_t s2 = [] {
        cudaStream_t s;
        cudaStreamCreateWithFlags(&s, cudaStreamNonBlocking);
        return s;
    }();
    static cudaEvent_t eFork = [] {
        cudaEvent_t e;
        cudaEventCreateWithFlags(&e, cudaEventDisableTiming);
        return e;
    }();
    static cudaEvent_t eJoin = [] {
        cudaEvent_t e;
        cudaEventCreateWithFlags(&e, cudaEventDisableTiming);
        return e;
    }();

    // fork
    cudaEventRecord(eFork, 0);
    cudaStreamWaitEvent(s2, eFork, 0);

    // branch B (stream s2): compaction + act + W4 transpose + bias3
    zero_flags_kernel<<<KTOK / 256, 256, 0, s2>>>();
    mark_kernel<<<KTOK / 256, 256, 0, s2>>>(parent);
    scan_kernel<<<1, 512, 0, s2>>>();
    act_kernel<<<KTOK, 256, 0, s2>>>(positions, W1, b1);
    transpose_hi_kernel<<<dim3(1024 / 32, 2048 / 32), dim3(32, 8), 0, s2>>>(
        W4, dW4th, 2048, 1024);
    bias3_part_kernel<<<dim3(8, 16), 256, 0, s2>>>(W3, b2);
    bias3_reduce_kernel<<<8, 256, 0, s2>>>(b3);
    cudaEventRecord(eJoin, s2);

    // branch A (stream 0): W3 chain -> B'
    transpose_w3_kernel<<<dim3(2048 / 32, 4096 / 32), dim3(32, 8)>>>(W3);
    split_w2_kernel<<<(512 * 1024) / 256, 256>>>(W2);
    hmma_gemm_kernel<1><<<dim3(512 / BN, 4096 / BM), NTHREADS, DYN_SMEM>>>(
        dW3th, dW2h, dBp, nullptr, 1024, 4096, 1024, 1536);

    // join
    cudaStreamWaitEvent(0, eJoin, 0);

    // --- merged U+V GEMM: y<128 = Vc (gathered, early-exit), y>=128 = U ---
    hmma_gemm_kernel<3><<<dim3(2048 / BN, 256), NTHREADS, DYN_SMEM>>>(
        dAph, dBp, dU, dVc, 1536, 1536, 1536, 2048);

    // --- fused final: out = relu(U + Vc[inv[par]] + bias3) @ W4t^T + b4 ---
    fused_final_kernel<<<dim3(1024 / BN, KTOK / BM), NTHREADS, F_DYN>>>(
        dU, dVc, dW4th, parent, dbias3, b4, out);
}

// round 16
// speedup vs baseline: 1.0110x; 1.0110x over previous
#include <cuda_runtime.h>
#include <cuda_fp16.h>
#include <math.h>
#include <stdint.h>

#define KTOK 16384

// ---------------------------------------------------------------------------
// Scratch (__device__ globals per allocation rules)
// ---------------------------------------------------------------------------
__device__ __half g_Aph[(size_t)KTOK * 1536];        // [H | gamma] hi
__device__ __half g_Bp[(size_t)4096 * 1536];         // B'
__device__ __half g_W2h[512 * 1024];                 // W2 hi
__device__ __half g_W3th[(size_t)2048 * 4096];       // W3^T hi
__device__ __half g_W4th[(size_t)1024 * 2048];       // W4^T hi
__device__ float  g_b3part[16 * 2048];
__device__ float  g_bias3[2048];
__device__ __half g_U[(size_t)KTOK * 2048];          // U = A'@B'u
__device__ __half g_Vc[(size_t)KTOK * 2048];         // compacted V rows
__device__ int    g_flag[KTOK];
__device__ int    g_rows[KTOK];                      // compacted parent rows
__device__ int    g_inv[KTOK];                       // k -> compact position
__device__ int    g_count;

// ---------------------------------------------------------------------------
// PTX primitives (sm_80-era; compile under compute_103)
// ---------------------------------------------------------------------------
__device__ __forceinline__ uint32_t smem_u32(const void* p) {
    uint32_t a;
    asm("{ .reg .u64 t; cvta.to.shared.u64 t, %1; cvt.u32.u64 %0, t; }" : "=r"(a) : "l"(p));
    return a;
}
__device__ __forceinline__ void cp_async16(uint32_t dst, const void* src) {
    asm volatile("cp.async.cg.shared.global [%0], [%1], 16;" :: "r"(dst), "l"(src));
}
#define CP_COMMIT() asm volatile("cp.async.commit_group;" ::: "memory")
#define CP_WAIT(n)  asm volatile("cp.async.wait_group %0;" :: "n"(n) : "memory")

__device__ __forceinline__ void ldsm_x4(uint32_t* r, uint32_t addr) {
    asm volatile("ldmatrix.sync.aligned.m8n8.x4.shared.b16 {%0,%1,%2,%3}, [%4];"
                 : "=r"(r[0]), "=r"(r[1]), "=r"(r[2]), "=r"(r[3]) : "r"(addr));
}
__device__ __forceinline__ void mma16816(float* d, const uint32_t* a,
                                         uint32_t b0, uint32_t b1) {
    asm volatile("mma.sync.aligned.m16n8k16.row.col.f32.f16.f16.f32 "
                 "{%0,%1,%2,%3}, {%4,%5,%6,%7}, {%8,%9}, {%0,%1,%2,%3};"
                 : "+f"(d[0]), "+f"(d[1]), "+f"(d[2]), "+f"(d[3])
                 : "r"(a[0]), "r"(a[1]), "r"(a[2]), "r"(a[3]), "r"(b0), "r"(b1));
}

// ---------------------------------------------------------------------------
// Parent-row compaction: zero -> mark -> single-block scan (deterministic)
// ---------------------------------------------------------------------------
__global__ void zero_flags_kernel() {
    int i = blockIdx.x * blockDim.x + threadIdx.x;   // KTOK threads
    g_flag[i] = 0;
    g_rows[i] = 0;
}
__global__ void mark_kernel(const int* __restrict__ parent) {
    int i = blockIdx.x * blockDim.x + threadIdx.x;
    g_flag[parent[i]] = 1;
}
__global__ void scan_kernel() {
    __shared__ int sc[512];
    int t = threadIdx.x;
    int base = t * 32;
    int cnt = 0;
#pragma unroll
    for (int i = 0; i < 32; i++) cnt += g_flag[base + i];
    sc[t] = cnt;
    __syncthreads();
    for (int off = 1; off < 512; off <<= 1) {
        int v = sc[t];
        int add = (t >= off) ? sc[t - off] : 0;
        __syncthreads();
        sc[t] = v + add;
        __syncthreads();
    }
    int pos = sc[t] - cnt;   // exclusive prefix
    if (t == 511) g_count = sc[511];
#pragma unroll
    for (int i = 0; i < 32; i++) {
        int k = base + i;
        if (g_flag[k]) {
            g_rows[pos] = k;
            g_inv[k] = pos;
            pos++;
        }
    }
}

// ---------------------------------------------------------------------------
// Activations, one block per row r
// ---------------------------------------------------------------------------
__global__ void act_kernel(const float* __restrict__ pos,
                           const float* __restrict__ W1,
                           const float* __restrict__ b1) {
    int r = blockIdx.x;
    int t = threadIdx.x;
    float p0 = pos[r * 3 + 0];
    float p1 = pos[r * 3 + 1];
    float p2 = pos[r * 3 + 2];
    __half* rowp = g_Aph + (size_t)r * 1536;
#pragma unroll
    for (int j = t; j < 512; j += 256) {
        float a = b1[j];
        a = fmaf(p0, W1[j], a);
        a = fmaf(p1, W1[512 + j], a);
        a = fmaf(p2, W1[1024 + j], a);
        rowp[j] = __float2half_rn(fmaxf(a, 0.0f));
    }
#pragma unroll
    for (int i = t; i < 512; i += 256) {
        float inv = exp2f(-(float)i * (13.287712379549449f / 512.0f));
        float s, c;
        sincosf((float)r * inv, &s, &c);
        *(__half2*)(rowp + 512 + 2 * i) =
            __halves2half2(__float2half_rn(s), __float2half_rn(c));
    }
}

// ---------------------------------------------------------------------------
// W3 transpose (hi only) fused with B' gamma-column scatter
// ---------------------------------------------------------------------------
__global__ void transpose_w3_kernel(const float* __restrict__ in) {
    __shared__ float tile[32][33];
    int c = blockIdx.x * 32 + threadIdx.x;
    int r0 = blockIdx.y * 32;
#pragma unroll
    for (int k = 0; k < 32; k += 8)
        tile[threadIdx.y + k][threadIdx.x] = in[(size_t)(r0 + threadIdx.y + k) * 2048 + c];
    __syncthreads();
    int m0 = blockIdx.x * 32;
    int j = r0 + threadIdx.x;
#pragma unroll
    for (int k = 0; k < 32; k += 8) {
        int m = m0 + threadIdx.y + k;
        __half h = __float2half_rn(tile[threadIdx.x][threadIdx.y + k]);
        g_W3th[(size_t)m * 4096 + j] = h;
        if (j >= 1024 && j < 2048)
            g_Bp[(size_t)m * 1536 + 512 + (j - 1024)] = h;
        else if (j >= 3072)
            g_Bp[(size_t)(2048 + m) * 1536 + 512 + (j - 3072)] = h;
    }
}

// generic transpose (hi only): in fp32 [R,C] -> out fp16 [C,R]
__global__ void transpose_hi_kernel(const float* __restrict__ in,
                                    __half* __restrict__ oh, int R, int C) {
    __shared__ float tile[32][33];
    int c = blockIdx.x * 32 + threadIdx.x;
    int r0 = blockIdx.y * 32;
#pragma unroll
    for (int k = 0; k < 32; k += 8)
        tile[threadIdx.y + k][threadIdx.x] = in[(size_t)(r0 + threadIdx.y + k) * C + c];
    __syncthreads();
    int orow0 = blockIdx.x * 32;
    int ocol = r0 + threadIdx.x;
#pragma unroll
    for (int k = 0; k < 32; k += 8)
        oh[(size_t)(orow0 + threadIdx.y + k) * R + ocol] =
            __float2half_rn(tile[threadIdx.x][threadIdx.y + k]);
}

__global__ void split_w2_kernel(const float* __restrict__ W2) {
    int idx = blockIdx.x * blockDim.x + threadIdx.x;
    g_W2h[idx] = __float2half_rn(W2[idx]);
}

// bias3 two-phase deterministic reduction
__global__ void bias3_part_kernel(const float* __restrict__ W3,
                                  const float* __restrict__ b2) {
    int m = blockIdx.x * blockDim.x + threadIdx.x;
    int j0 = blockIdx.y * 64;
    float s = 0.0f;
#pragma unroll 8
    for (int j = j0; j < j0 + 64; j++)
        s += b2[j] * (W3[(size_t)j * 2048 + m] + W3[(size_t)(2048 + j) * 2048 + m]);
    g_b3part[blockIdx.y * 2048 + m] = s;
}
__global__ void bias3_reduce_kernel(const float* __restrict__ b3) {
    int m = blockIdx.x * blockDim.x + threadIdx.x;
    float s = b3[m];
#pragma unroll
    for (int c = 0; c < 16; c++) s += g_b3part[c * 2048 + m];
    g_bias3[m] = s;
}

// ---------------------------------------------------------------------------
// HMMA GEMM: C[M,N] = A[M,Kd] @ Bt[N,Kd]^T, 1-pass fp16, OUT fp16.
// BM=128, BN=256, BK=64; 512 threads, 16 warps (4x4), warp tile 32x64;
// 4-stage cp.async, single barrier/chunk.
// MODE 0: plain. MODE 1: SPLITROW (prep). MODE 2: A rows gathered via
// g_rows[] with early-exit past g_count (compacted V GEMM).
// ---------------------------------------------------------------------------
#define BM 128
#define BN 256
#define BKK 64
#define NTHREADS 512
#define A_TILE 16384
#define B_TILE 32768
#define STAGE_BYTES (A_TILE + B_TILE)
#define DYN_SMEM (4 * STAGE_BYTES)

__device__ __forceinline__ uint32_t sw_off(int row, int ch) {
    return (uint32_t)(row * 128 + ((ch ^ (row & 7)) << 4));
}
template <int ROWS>
__device__ __forceinline__ void load_tile(uint32_t sbase, const __half* g,
                                          int ldk, int tid) {
#pragma unroll
    for (int i = 0; i < ROWS * 8 / NTHREADS; i++) {
        int id = tid + i * NTHREADS;
        int row = id >> 3, ch = id & 7;
        cp_async16(sbase + sw_off(row, ch), g + (size_t)row * ldk + ch * 8);
    }
}

template <int MODE>
__global__ __launch_bounds__(NTHREADS, 1) void hmma_gemm_kernel(
    const __half* __restrict__ Ah, const __half* __restrict__ Bh,
    __half* __restrict__ Ch, int Kd, int ldA, int ldB, int ldC) {
    __shared__ int srow[BM];
    extern __shared__ char smem[];
    const uint32_t sbase = smem_u32(smem);

    const int tid = threadIdx.x;
    const int wid = tid >> 5;
    const int lane = tid & 31;
    const int wm = wid >> 2;          // 0..3 (32-row slice)
    const int wn = wid & 3;           // 0..3 (64-col slice)

    const size_t m0 = (size_t)blockIdx.y * BM;
    const size_t n0 = (size_t)blockIdx.x * BN;
    const int NC = Kd / BKK;

    if (MODE == 2) {
        if ((int)m0 >= g_count) return;
        if (tid < BM) srow[tid] = g_rows[m0 + tid];
        __syncthreads();
    }

    const __half* gAh = (MODE == 1 && m0 >= 2048)
                            ? (Ah + (m0 - 2048) * ldA + 2048)
                            : (MODE == 2 ? Ah : Ah + m0 * ldA);
    const __half* gBh = Bh + n0 * ldB;

    // A loader helper (gather for MODE 2)
    auto load_a = [&](uint32_t sb, int k0) {
#pragma unroll
        for (int i = 0; i < BM * 8 / NTHREADS; i++) {   // 2
            int id = tid + i * NTHREADS;
            int row = id >> 3, ch = id & 7;
            const __half* src = (MODE == 2)
                ? gAh + (size_t)srow[row] * ldA + k0 + ch * 8
                : gAh + (size_t)row * ldA + k0 + ch * 8;
            cp_async16(sb + sw_off(row, ch), src);
        }
    };

#pragma unroll
    for (int s = 0; s < 3; s++) {
        uint32_t sb = sbase + s * STAGE_BYTES;
        int k0 = s * BKK;
        load_a(sb, k0);
        load_tile<256>(sb + A_TILE, gBh + k0, ldB, tid);
        CP_COMMIT();
    }

    float acc[2][8][4];
#pragma unroll
    for (int mi = 0; mi < 2; mi++)
#pragma unroll
        for (int ni = 0; ni < 8; ni++)
#pragma unroll
            for (int q = 0; q < 4; q++) acc[mi][ni][q] = 0.0f;

    const int a_row = wm * 32 + (lane & 15);
    const int b_row = wn * 64 + (lane & 15);
    const int kc_lane = lane >> 4;

    for (int c = 0; c < NC; c++) {
        CP_WAIT(2);
        __syncthreads();   // protects stage (c-1)&3 (prefetch target) too

        int pf = c + 3;
        if (pf < NC) {
            uint32_t sb = sbase + (pf & 3) * STAGE_BYTES;
            int k0 = pf * BKK;
            load_a(sb, k0);
            load_tile<256>(sb + A_TILE, gBh + k0, ldB, tid);
        }
        CP_COMMIT();

        uint32_t sA = sbase + (c & 3) * STAGE_BYTES;
        uint32_t sB = sA + A_TILE;

#pragma unroll
        for (int ks = 0; ks < 4; ks++) {
            int kc = ks * 2 + kc_lane;
            uint32_t b_h[4][4];
#pragma unroll
            for (int j = 0; j < 4; j++)
                ldsm_x4(b_h[j], sB + sw_off(b_row + j * 16, kc));
#pragma unroll
            for (int mi = 0; mi < 2; mi++) {
                uint32_t a_h[4];
                ldsm_x4(a_h, sA + sw_off(a_row + mi * 16, kc));
#pragma unroll
                for (int ni = 0; ni < 8; ni++) {
                    int j = ni >> 1, s = ni & 1;
                    mma16816(acc[mi][ni], a_h, b_h[j][s], b_h[j][s + 2]);
                }
            }
        }
    }

    const int tm = lane >> 2;
    const int tn = lane & 3;
#pragma unroll
    for (int mi = 0; mi < 2; mi++) {
#pragma unroll
        for (int h = 0; h < 2; h++) {
            size_t row = m0 + wm * 32 + mi * 16 + h * 8 + tm;
#pragma unroll
            for (int ni = 0; ni < 8; ni++) {
                size_t col = n0 + wn * 64 + ni * 8 + tn * 2;
                *(__half2*)(Ch + row * ldC + col) =
                    __halves2half2(__float2half_rn(acc[mi][ni][h * 2 + 0]),
                                   __float2half_rn(acc[mi][ni][h * 2 + 1]));
            }
        }
    }
}

// ---------------------------------------------------------------------------
// Fused final GEMM: out[K,1024] = relu(U[k] + Vc[inv[par[k]]] + bias3) @ W4t^T + b4
// 512 threads, warp grid 4x4, warp tile 32x64; 3 stages.
// ---------------------------------------------------------------------------
#define F_STAGE (2 * A_TILE + B_TILE)
#define F_TILES_OFF 4608   // 512B parent + 4KB bias, 128B-aligned
#define F_DYN (F_TILES_OFF + 3 * F_STAGE)

__global__ __launch_bounds__(NTHREADS, 1) void fused_final_kernel(
    const __half* __restrict__ U, const __half* __restrict__ Vc,
    const __half* __restrict__ W4t,
    const int* __restrict__ parent, const float* __restrict__ bias3,
    const float* __restrict__ b4, float* __restrict__ out) {
    extern __shared__ char smem[];
    int* spar = (int*)smem;
    __half2* sbias = (__half2*)(smem + 512);
    const uint32_t tbase = smem_u32(smem) + F_TILES_OFF;

    const int tid = threadIdx.x;
    const int wid = tid >> 5;
    const int lane = tid & 31;
    const int wm = wid >> 2;
    const int wn = wid & 3;

    const size_t m0 = (size_t)blockIdx.y * BM;
    const size_t n0 = (size_t)blockIdx.x * BN;
    const int NC = 2048 / BKK;   // 32

    if (tid < 128) spar[tid] = g_inv[parent[m0 + tid]];
#pragma unroll
    for (int i = tid; i < 1024; i += NTHREADS)
        sbias[i] = __halves2half2(__float2half_rn(bias3[2 * i]),
                                  __float2half_rn(bias3[2 * i + 1]));
    __syncthreads();

    const __half* gU = U + m0 * 2048;
    const __half* gB = W4t + n0 * 2048;

    auto load_stage = [&](int stage, int k0) {
        uint32_t sb = tbase + stage * F_STAGE;
#pragma unroll
        for (int i = 0; i < 2; i++) {
            int id = tid + i * NTHREADS;
            int row = id >> 3, ch = id & 7;
            cp_async16(sb + sw_off(row, ch), gU + (size_t)row * 2048 + k0 + ch * 8);
        }
#pragma unroll
        for (int i = 0; i < 2; i++) {
            int id = tid + i * NTHREADS;
            int row = id >> 3, ch = id & 7;
            cp_async16(sb + A_TILE + sw_off(row, ch),
                       Vc + (size_t)spar[row] * 2048 + k0 + ch * 8);
        }
#pragma unroll
        for (int i = 0; i < 4; i++) {
            int id = tid + i * NTHREADS;
            int row = id >> 3, ch = id & 7;
            cp_async16(sb + 2 * A_TILE + sw_off(row, ch), gB + (size_t)row * 2048 + k0 + ch * 8);
        }
        CP_COMMIT();
    };

    load_stage(0, 0);
    load_stage(1, BKK);

    float acc[2][8][4];
#pragma unroll
    for (int mi = 0; mi < 2; mi++)
#pragma unroll
        for (int ni = 0; ni < 8; ni++)
#pragma unroll
            for (int q = 0; q < 4; q++) acc[mi][ni][q] = 0.0f;

    const int a_row = wm * 32 + (lane & 15);
    const int b_row = wn * 64 + (lane & 15);
    const int kc_lane = lane >> 4;
    const __half2 zero2 = __float2half2_rn(0.0f);

    for (int c = 0; c < NC; c++) {
        CP_WAIT(1);
        __syncthreads();   // single barrier per chunk

        if (c + 2 < NC) load_stage((c + 2) % 3, (c + 2) * BKK);
        else CP_COMMIT();

        uint32_t sU = tbase + (c % 3) * F_STAGE;
        uint32_t sV = sU + A_TILE;
        uint32_t sB = sU + 2 * A_TILE;

#pragma unroll
        for (int ks = 0; ks < 4; ks++) {
            int kc = ks * 2 + kc_lane;
            __half2 b_lo = sbias[c * 32 + ks * 8 + (lane & 3)];
            __half2 b_hi = sbias[c * 32 + ks * 8 + 4 + (lane & 3)];

            uint32_t b_h[4][4];
#pragma unroll
            for (int j = 0; j < 4; j++)
                ldsm_x4(b_h[j], sB + sw_off(b_row + j * 16, kc));
#pragma unroll
            for (int mi = 0; mi < 2; mi++) {
                uint32_t u[4], v[4], a_h[4];
                uint32_t off = sw_off(a_row + mi * 16, kc);
                ldsm_x4(u, sU + off);
                ldsm_x4(v, sV + off);
#pragma unroll
                for (int q = 0; q < 4; q++) {
                    __half2 s = __hadd2(*(__half2*)&u[q], *(__half2*)&v[q]);
                    s = __hadd2(s, (q < 2) ? b_lo : b_hi);
                    s = __hmax2(s, zero2);
                    a_h[q] = *(uint32_t*)&s;
                }
#pragma unroll
                for (int ni = 0; ni < 8; ni++) {
                    int j = ni >> 1, s = ni & 1;
                    mma16816(acc[mi][ni], a_h, b_h[j][s], b_h[j][s + 2]);
                }
            }
        }
    }

    const int tm = lane >> 2;
    const int tn = lane & 3;
#pragma unroll
    for (int mi = 0; mi < 2; mi++) {
#pragma unroll
        for (int h = 0; h < 2; h++) {
            size_t row = m0 + wm * 32 + mi * 16 + h * 8 + tm;
#pragma unroll
            for (int ni = 0; ni < 8; ni++) {
                size_t col = n0 + wn * 64 + ni * 8 + tn * 2;
                float2 bv = *(const float2*)(b4 + col);
                *(float2*)(out + row * 1024 + col) =
                    make_float2(acc[mi][ni][h * 2 + 0] + bv.x,
                                acc[mi][ni][h * 2 + 1] + bv.y);
            }
        }
    }
}

// ---------------------------------------------------------------------------
// Launch: two-stream DAG.
//   stream 0: W3 chain -> prep GEMM -> [eBp] ... wait eJoin -> U GEMM
//             -> wait eV -> fused_final
//   s2:       compaction/act/W4t/bias3 -> [eJoin] -> wait eBp -> V GEMM -> [eV]
// ---------------------------------------------------------------------------
extern "C" void kernel_launch(void* const* d_in, const int* in_sizes, int n_in,
                              void* d_out, int out_size) {
    const float* positions = (const float*)d_in[0];
    const int*   parent    = (const int*)d_in[1];
    const float* W1 = (const float*)d_in[2];
    const float* b1 = (const float*)d_in[3];
    const float* W2 = (const float*)d_in[4];
    const float* b2 = (const float*)d_in[5];
    const float* W3 = (const float*)d_in[6];
    const float* b3 = (const float*)d_in[7];
    const float* W4 = (const float*)d_in[8];
    const float* b4 = (const float*)d_in[9];
    float* out = (float*)d_out;

    __half *dAph, *dBp, *dW2h, *dW3th, *dW4th, *dU, *dVc;
    cudaGetSymbolAddress((void**)&dAph, g_Aph);
    cudaGetSymbolAddress((void**)&dBp, g_Bp);
    cudaGetSymbolAddress((void**)&dW2h, g_W2h);
    cudaGetSymbolAddress((void**)&dW3th, g_W3th);
    cudaGetSymbolAddress((void**)&dW4th, g_W4th);
    cudaGetSymbolAddress((void**)&dU, g_U);
    cudaGetSymbolAddress((void**)&dVc, g_Vc);
    float* dbias3;
    cudaGetSymbolAddress((void**)&dbias3, g_bias3);

    cudaFuncSetAttribute(hmma_gemm_kernel<0>,
                         cudaFuncAttributeMaxDynamicSharedMemorySize, DYN_SMEM);
    cudaFuncSetAttribute(hmma_gemm_kernel<1>,
                         cudaFuncAttributeMaxDynamicSharedMemorySize, DYN_SMEM);
    cudaFuncSetAttribute(hmma_gemm_kernel<2>,
                         cudaFuncAttributeMaxDynamicSharedMemorySize, DYN_SMEM);
    cudaFuncSetAttribute(fused_final_kernel,
                         cudaFuncAttributeMaxDynamicSharedMemorySize, F_DYN);

    // persistent side-stream + events (host handles only; same GPU work each call)
    static cudaStream_t s2 = [] {
        cudaStream_t s;
        cudaStreamCreateWithFlags(&s, cudaStreamNonBlocking);
        return s;
    }();
    static cudaEvent_t eFork = [] {
        cudaEvent_t e;
        cudaEventCreateWithFlags(&e, cudaEventDisableTiming);
        return e;
    }();
    static cudaEvent_t eJoin = [] {
        cudaEvent_t e;
        cudaEventCreateWithFlags(&e, cudaEventDisableTiming);
        return e;
    }();
    static cudaEvent_t eBp = [] {
        cudaEvent_t e;
        cudaEventCreateWithFlags(&e, cudaEventDisableTiming);
        return e;
    }();
    static cudaEvent_t eV = [] {
        cudaEvent_t e;
        cudaEventCreateWithFlags(&e, cudaEventDisableTiming);
        return e;
    }();

    // fork
    cudaEventRecord(eFork, 0);
    cudaStreamWaitEvent(s2, eFork, 0);

    // branch B (s2): compaction + act + W4 transpose + bias3
    zero_flags_kernel<<<KTOK / 256, 256, 0, s2>>>();
    mark_kernel<<<KTOK / 256, 256, 0, s2>>>(parent);
    scan_kernel<<<1, 512, 0, s2>>>();
    act_kernel<<<KTOK, 256, 0, s2>>>(positions, W1, b1);
    transpose_hi_kernel<<<dim3(1024 / 32, 2048 / 32), dim3(32, 8), 0, s2>>>(
        W4, dW4th, 2048, 1024);
    bias3_part_kernel<<<dim3(8, 16), 256, 0, s2>>>(W3, b2);
    bias3_reduce_kernel<<<8, 256, 0, s2>>>(b3);
    cudaEventRecord(eJoin, s2);

    // branch A (stream 0): W3 chain -> B'
    transpose_w3_kernel<<<dim3(2048 / 32, 4096 / 32), dim3(32, 8)>>>(W3);
    split_w2_kernel<<<(512 * 1024) / 256, 256>>>(W2);
    hmma_gemm_kernel<1><<<dim3(512 / BN, 4096 / BM), NTHREADS, DYN_SMEM>>>(
        dW3th, dW2h, dBp, 1024, 4096, 1024, 1536);
    cudaEventRecord(eBp, 0);

    // V GEMM on s2 (needs B' from stream 0; act/scan already on s2)
    cudaStreamWaitEvent(s2, eBp, 0);
    hmma_gemm_kernel<2><<<dim3(2048 / BN, KTOK / BM), NTHREADS, DYN_SMEM, s2>>>(
        dAph, dBp + (size_t)2048 * 1536, dVc, 1536, 1536, 1536, 2048);
    cudaEventRecord(eV, s2);

    // U GEMM on stream 0 (needs act from branch B)
    cudaStreamWaitEvent(0, eJoin, 0);
    hmma_gemm_kernel<0><<<dim3(2048 / BN, KTOK / BM), NTHREADS, DYN_SMEM>>>(
        dAph, dBp, dU, 1536, 1536, 1536, 2048);

    // fused final (needs U on stream 0 + Vc from s2)
    cudaStreamWaitEvent(0, eV, 0);
    fused_final_kernel<<<dim3(1024 / BN, KTOK / BM), NTHREADS, F_DYN>>>(
        dU, dVc, dW4th, parent, dbias3, b4, out);
}

// round 17
// speedup vs baseline: 1.0301x; 1.0189x over previous
#include <cuda_runtime.h>
#include <cuda_fp16.h>
#include <math.h>
#include <stdint.h>

#define KTOK 16384

// ---------------------------------------------------------------------------
// Scratch (__device__ globals per allocation rules)
// ---------------------------------------------------------------------------
__device__ __half g_Aph[(size_t)KTOK * 1536];        // [H | gamma] hi
__device__ __half g_Bp[(size_t)4096 * 1536];         // B'
__device__ __half g_W2h[512 * 1024];                 // W2 hi
__device__ __half g_W3th[(size_t)2048 * 4096];       // W3^T hi
__device__ __half g_W4th[(size_t)1024 * 2048];       // W4^T hi
__device__ float  g_b3part[16 * 2048];
__device__ float  g_bias3[2048];
__device__ __half g_U[(size_t)KTOK * 2048];          // U = A'@B'u
__device__ __half g_Vc[(size_t)KTOK * 2048];         // compacted V rows
__device__ int    g_flag[KTOK];
__device__ int    g_rows[KTOK];                      // compacted parent rows
__device__ int    g_inv[KTOK];                       // k -> compact position
__device__ int    g_count;

// ---------------------------------------------------------------------------
// PTX primitives (sm_80-era; compile under compute_103)
// ---------------------------------------------------------------------------
__device__ __forceinline__ uint32_t smem_u32(const void* p) {
    uint32_t a;
    asm("{ .reg .u64 t; cvta.to.shared.u64 t, %1; cvt.u32.u64 %0, t; }" : "=r"(a) : "l"(p));
    return a;
}
__device__ __forceinline__ void cp_async16(uint32_t dst, const void* src) {
    asm volatile("cp.async.cg.shared.global [%0], [%1], 16;" :: "r"(dst), "l"(src));
}
#define CP_COMMIT() asm volatile("cp.async.commit_group;" ::: "memory")
#define CP_WAIT(n)  asm volatile("cp.async.wait_group %0;" :: "n"(n) : "memory")

__device__ __forceinline__ void ldsm_x4(uint32_t* r, uint32_t addr) {
    asm volatile("ldmatrix.sync.aligned.m8n8.x4.shared.b16 {%0,%1,%2,%3}, [%4];"
                 : "=r"(r[0]), "=r"(r[1]), "=r"(r[2]), "=r"(r[3]) : "r"(addr));
}
__device__ __forceinline__ void mma16816(float* d, const uint32_t* a,
                                         uint32_t b0, uint32_t b1) {
    asm volatile("mma.sync.aligned.m16n8k16.row.col.f32.f16.f16.f32 "
                 "{%0,%1,%2,%3}, {%4,%5,%6,%7}, {%8,%9}, {%0,%1,%2,%3};"
                 : "+f"(d[0]), "+f"(d[1]), "+f"(d[2]), "+f"(d[3])
                 : "r"(a[0]), "r"(a[1]), "r"(a[2]), "r"(a[3]), "r"(b0), "r"(b1));
}

// ---------------------------------------------------------------------------
// Parent-row compaction: zero -> mark -> single-block scan (deterministic)
// ---------------------------------------------------------------------------
__global__ void zero_flags_kernel() {
    int i = blockIdx.x * blockDim.x + threadIdx.x;   // KTOK threads
    g_flag[i] = 0;
    g_rows[i] = 0;
}
__global__ void mark_kernel(const int* __restrict__ parent) {
    int i = blockIdx.x * blockDim.x + threadIdx.x;
    g_flag[parent[i]] = 1;
}
__global__ void scan_kernel() {
    __shared__ int sc[512];
    int t = threadIdx.x;
    int base = t * 32;
    int cnt = 0;
#pragma unroll
    for (int i = 0; i < 32; i++) cnt += g_flag[base + i];
    sc[t] = cnt;
    __syncthreads();
    for (int off = 1; off < 512; off <<= 1) {
        int v = sc[t];
        int add = (t >= off) ? sc[t - off] : 0;
        __syncthreads();
        sc[t] = v + add;
        __syncthreads();
    }
    int pos = sc[t] - cnt;   // exclusive prefix
    if (t == 511) g_count = sc[511];
#pragma unroll
    for (int i = 0; i < 32; i++) {
        int k = base + i;
        if (g_flag[k]) {
            g_rows[pos] = k;
            g_inv[k] = pos;
            pos++;
        }
    }
}

// ---------------------------------------------------------------------------
// Activations, one block per row r
// ---------------------------------------------------------------------------
__global__ void act_kernel(const float* __restrict__ pos,
                           const float* __restrict__ W1,
                           const float* __restrict__ b1) {
    int r = blockIdx.x;
    int t = threadIdx.x;
    float p0 = pos[r * 3 + 0];
    float p1 = pos[r * 3 + 1];
    float p2 = pos[r * 3 + 2];
    __half* rowp = g_Aph + (size_t)r * 1536;
#pragma unroll
    for (int j = t; j < 512; j += 256) {
        float a = b1[j];
        a = fmaf(p0, W1[j], a);
        a = fmaf(p1, W1[512 + j], a);
        a = fmaf(p2, W1[1024 + j], a);
        rowp[j] = __float2half_rn(fmaxf(a, 0.0f));
    }
#pragma unroll
    for (int i = t; i < 512; i += 256) {
        float inv = exp2f(-(float)i * (13.287712379549449f / 512.0f));
        float s, c;
        sincosf((float)r * inv, &s, &c);
        *(__half2*)(rowp + 512 + 2 * i) =
            __halves2half2(__float2half_rn(s), __float2half_rn(c));
    }
}

// ---------------------------------------------------------------------------
// W3 transpose (hi only) fused with B' gamma-column scatter
// ---------------------------------------------------------------------------
__global__ void transpose_w3_kernel(const float* __restrict__ in) {
    __shared__ float tile[32][33];
    int c = blockIdx.x * 32 + threadIdx.x;
    int r0 = blockIdx.y * 32;
#pragma unroll
    for (int k = 0; k < 32; k += 8)
        tile[threadIdx.y + k][threadIdx.x] = in[(size_t)(r0 + threadIdx.y + k) * 2048 + c];
    __syncthreads();
    int m0 = blockIdx.x * 32;
    int j = r0 + threadIdx.x;
#pragma unroll
    for (int k = 0; k < 32; k += 8) {
        int m = m0 + threadIdx.y + k;
        __half h = __float2half_rn(tile[threadIdx.x][threadIdx.y + k]);
        g_W3th[(size_t)m * 4096 + j] = h;
        if (j >= 1024 && j < 2048)
            g_Bp[(size_t)m * 1536 + 512 + (j - 1024)] = h;
        else if (j >= 3072)
            g_Bp[(size_t)(2048 + m) * 1536 + 512 + (j - 3072)] = h;
    }
}

// generic transpose (hi only): in fp32 [R,C] -> out fp16 [C,R]
__global__ void transpose_hi_kernel(const float* __restrict__ in,
                                    __half* __restrict__ oh, int R, int C) {
    __shared__ float tile[32][33];
    int c = blockIdx.x * 32 + threadIdx.x;
    int r0 = blockIdx.y * 32;
#pragma unroll
    for (int k = 0; k < 32; k += 8)
        tile[threadIdx.y + k][threadIdx.x] = in[(size_t)(r0 + threadIdx.y + k) * C + c];
    __syncthreads();
    int orow0 = blockIdx.x * 32;
    int ocol = r0 + threadIdx.x;
#pragma unroll
    for (int k = 0; k < 32; k += 8)
        oh[(size_t)(orow0 + threadIdx.y + k) * R + ocol] =
            __float2half_rn(tile[threadIdx.x][threadIdx.y + k]);
}

__global__ void split_w2_kernel(const float* __restrict__ W2) {
    int idx = blockIdx.x * blockDim.x + threadIdx.x;
    g_W2h[idx] = __float2half_rn(W2[idx]);
}

// bias3 two-phase deterministic reduction
__global__ void bias3_part_kernel(const float* __restrict__ W3,
                                  const float* __restrict__ b2) {
    int m = blockIdx.x * blockDim.x + threadIdx.x;
    int j0 = blockIdx.y * 64;
    float s = 0.0f;
#pragma unroll 8
    for (int j = j0; j < j0 + 64; j++)
        s += b2[j] * (W3[(size_t)j * 2048 + m] + W3[(size_t)(2048 + j) * 2048 + m]);
    g_b3part[blockIdx.y * 2048 + m] = s;
}
__global__ void bias3_reduce_kernel(const float* __restrict__ b3) {
    int m = blockIdx.x * blockDim.x + threadIdx.x;
    float s = b3[m];
#pragma unroll
    for (int c = 0; c < 16; c++) s += g_b3part[c * 2048 + m];
    g_bias3[m] = s;
}

// ---------------------------------------------------------------------------
// HMMA GEMM: C[M,N] = A[M,Kd] @ Bt[N,Kd]^T, 1-pass fp16, OUT fp16.
// BM=128, BN=256, BK=64; 512 threads, 16 warps (4x4), warp tile 32x64;
// 4-stage cp.async, single barrier/chunk.
// MODE 0: plain. MODE 2: A rows gathered via g_rows[] with early-exit past
// g_count (compacted V GEMM).
// ---------------------------------------------------------------------------
#define BM 128
#define BN 256
#define BKK 64
#define NTHREADS 512
#define A_TILE 16384
#define B_TILE 32768
#define STAGE_BYTES (A_TILE + B_TILE)
#define DYN_SMEM (4 * STAGE_BYTES)

__device__ __forceinline__ uint32_t sw_off(int row, int ch) {
    return (uint32_t)(row * 128 + ((ch ^ (row & 7)) << 4));
}
template <int ROWS>
__device__ __forceinline__ void load_tile(uint32_t sbase, const __half* g,
                                          int ldk, int tid) {
#pragma unroll
    for (int i = 0; i < ROWS * 8 / NTHREADS; i++) {
        int id = tid + i * NTHREADS;
        int row = id >> 3, ch = id & 7;
        cp_async16(sbase + sw_off(row, ch), g + (size_t)row * ldk + ch * 8);
    }
}

template <int MODE>
__global__ __launch_bounds__(NTHREADS, 1) void hmma_gemm_kernel(
    const __half* __restrict__ Ah, const __half* __restrict__ Bh,
    __half* __restrict__ Ch, int Kd, int ldA, int ldB, int ldC) {
    __shared__ int srow[BM];
    extern __shared__ char smem[];
    const uint32_t sbase = smem_u32(smem);

    const int tid = threadIdx.x;
    const int wid = tid >> 5;
    const int lane = tid & 31;
    const int wm = wid >> 2;          // 0..3 (32-row slice)
    const int wn = wid & 3;           // 0..3 (64-col slice)

    const size_t m0 = (size_t)blockIdx.y * BM;
    const size_t n0 = (size_t)blockIdx.x * BN;
    const int NC = Kd / BKK;

    if (MODE == 2) {
        if ((int)m0 >= g_count) return;
        if (tid < BM) srow[tid] = g_rows[m0 + tid];
        __syncthreads();
    }

    const __half* gAh = (MODE == 2) ? Ah : Ah + m0 * ldA;
    const __half* gBh = Bh + n0 * ldB;

    // A loader helper (gather for MODE 2)
    auto load_a = [&](uint32_t sb, int k0) {
#pragma unroll
        for (int i = 0; i < BM * 8 / NTHREADS; i++) {   // 2
            int id = tid + i * NTHREADS;
            int row = id >> 3, ch = id & 7;
            const __half* src = (MODE == 2)
                ? gAh + (size_t)srow[row] * ldA + k0 + ch * 8
                : gAh + (size_t)row * ldA + k0 + ch * 8;
            cp_async16(sb + sw_off(row, ch), src);
        }
    };

#pragma unroll
    for (int s = 0; s < 3; s++) {
        uint32_t sb = sbase + s * STAGE_BYTES;
        int k0 = s * BKK;
        load_a(sb, k0);
        load_tile<256>(sb + A_TILE, gBh + k0, ldB, tid);
        CP_COMMIT();
    }

    float acc[2][8][4];
#pragma unroll
    for (int mi = 0; mi < 2; mi++)
#pragma unroll
        for (int ni = 0; ni < 8; ni++)
#pragma unroll
            for (int q = 0; q < 4; q++) acc[mi][ni][q] = 0.0f;

    const int a_row = wm * 32 + (lane & 15);
    const int b_row = wn * 64 + (lane & 15);
    const int kc_lane = lane >> 4;

    for (int c = 0; c < NC; c++) {
        CP_WAIT(2);
        __syncthreads();   // protects stage (c-1)&3 (prefetch target) too

        int pf = c + 3;
        if (pf < NC) {
            uint32_t sb = sbase + (pf & 3) * STAGE_BYTES;
            int k0 = pf * BKK;
            load_a(sb, k0);
            load_tile<256>(sb + A_TILE, gBh + k0, ldB, tid);
        }
        CP_COMMIT();

        uint32_t sA = sbase + (c & 3) * STAGE_BYTES;
        uint32_t sB = sA + A_TILE;

#pragma unroll
        for (int ks = 0; ks < 4; ks++) {
            int kc = ks * 2 + kc_lane;
            uint32_t b_h[4][4];
#pragma unroll
            for (int j = 0; j < 4; j++)
                ldsm_x4(b_h[j], sB + sw_off(b_row + j * 16, kc));
#pragma unroll
            for (int mi = 0; mi < 2; mi++) {
                uint32_t a_h[4];
                ldsm_x4(a_h, sA + sw_off(a_row + mi * 16, kc));
#pragma unroll
                for (int ni = 0; ni < 8; ni++) {
                    int j = ni >> 1, s = ni & 1;
                    mma16816(acc[mi][ni], a_h, b_h[j][s], b_h[j][s + 2]);
                }
            }
        }
    }

    const int tm = lane >> 2;
    const int tn = lane & 3;
#pragma unroll
    for (int mi = 0; mi < 2; mi++) {
#pragma unroll
        for (int h = 0; h < 2; h++) {
            size_t row = m0 + wm * 32 + mi * 16 + h * 8 + tm;
#pragma unroll
            for (int ni = 0; ni < 8; ni++) {
                size_t col = n0 + wn * 64 + ni * 8 + tn * 2;
                *(__half2*)(Ch + row * ldC + col) =
                    __halves2half2(__float2half_rn(acc[mi][ni][h * 2 + 0]),
                                   __float2half_rn(acc[mi][ni][h * 2 + 1]));
            }
        }
    }
}

// ---------------------------------------------------------------------------
// Fused final GEMM: out[K,1024] = relu(U[k] + Vc[inv[par[k]]] + bias3) @ W4t^T + b4
// 512 threads, warp grid 4x4, warp tile 32x64; 3 stages.
// ---------------------------------------------------------------------------
#define F_STAGE (2 * A_TILE + B_TILE)
#define F_TILES_OFF 4608   // 512B parent + 4KB bias, 128B-aligned
#define F_DYN (F_TILES_OFF + 3 * F_STAGE)

__global__ __launch_bounds__(NTHREADS, 1) void fused_final_kernel(
    const __half* __restrict__ U, const __half* __restrict__ Vc,
    const __half* __restrict__ W4t,
    const int* __restrict__ parent, const float* __restrict__ bias3,
    const float* __restrict__ b4, float* __restrict__ out) {
    extern __shared__ char smem[];
    int* spar = (int*)smem;
    __half2* sbias = (__half2*)(smem + 512);
    const uint32_t tbase = smem_u32(smem) + F_TILES_OFF;

    const int tid = threadIdx.x;
    const int wid = tid >> 5;
    const int lane = tid & 31;
    const int wm = wid >> 2;
    const int wn = wid & 3;

    const size_t m0 = (size_t)blockIdx.y * BM;
    const size_t n0 = (size_t)blockIdx.x * BN;
    const int NC = 2048 / BKK;   // 32

    if (tid < 128) spar[tid] = g_inv[parent[m0 + tid]];
#pragma unroll
    for (int i = tid; i < 1024; i += NTHREADS)
        sbias[i] = __halves2half2(__float2half_rn(bias3[2 * i]),
                                  __float2half_rn(bias3[2 * i + 1]));
    __syncthreads();

    const __half* gU = U + m0 * 2048;
    const __half* gB = W4t + n0 * 2048;

    auto load_stage = [&](int stage, int k0) {
        uint32_t sb = tbase + stage * F_STAGE;
#pragma unroll
        for (int i = 0; i < 2; i++) {
            int id = tid + i * NTHREADS;
            int row = id >> 3, ch = id & 7;
            cp_async16(sb + sw_off(row, ch), gU + (size_t)row * 2048 + k0 + ch * 8);
        }
#pragma unroll
        for (int i = 0; i < 2; i++) {
            int id = tid + i * NTHREADS;
            int row = id >> 3, ch = id & 7;
            cp_async16(sb + A_TILE + sw_off(row, ch),
                       Vc + (size_t)spar[row] * 2048 + k0 + ch * 8);
        }
#pragma unroll
        for (int i = 0; i < 4; i++) {
            int id = tid + i * NTHREADS;
            int row = id >> 3, ch = id & 7;
            cp_async16(sb + 2 * A_TILE + sw_off(row, ch), gB + (size_t)row * 2048 + k0 + ch * 8);
        }
        CP_COMMIT();
    };

    load_stage(0, 0);
    load_stage(1, BKK);

    float acc[2][8][4];
#pragma unroll
    for (int mi = 0; mi < 2; mi++)
#pragma unroll
        for (int ni = 0; ni < 8; ni++)
#pragma unroll
            for (int q = 0; q < 4; q++) acc[mi][ni][q] = 0.0f;

    const int a_row = wm * 32 + (lane & 15);
    const int b_row = wn * 64 + (lane & 15);
    const int kc_lane = lane >> 4;
    const __half2 zero2 = __float2half2_rn(0.0f);

    for (int c = 0; c < NC; c++) {
        CP_WAIT(1);
        __syncthreads();   // single barrier per chunk

        if (c + 2 < NC) load_stage((c + 2) % 3, (c + 2) * BKK);
        else CP_COMMIT();

        uint32_t sU = tbase + (c % 3) * F_STAGE;
        uint32_t sV = sU + A_TILE;
        uint32_t sB = sU + 2 * A_TILE;

#pragma unroll
        for (int ks = 0; ks < 4; ks++) {
            int kc = ks * 2 + kc_lane;
            __half2 b_lo = sbias[c * 32 + ks * 8 + (lane & 3)];
            __half2 b_hi = sbias[c * 32 + ks * 8 + 4 + (lane & 3)];

            uint32_t b_h[4][4];
#pragma unroll
            for (int j = 0; j < 4; j++)
                ldsm_x4(b_h[j], sB + sw_off(b_row + j * 16, kc));
#pragma unroll
            for (int mi = 0; mi < 2; mi++) {
                uint32_t u[4], v[4], a_h[4];
                uint32_t off = sw_off(a_row + mi * 16, kc);
                ldsm_x4(u, sU + off);
                ldsm_x4(v, sV + off);
#pragma unroll
                for (int q = 0; q < 4; q++) {
                    __half2 s = __hadd2(*(__half2*)&u[q], *(__half2*)&v[q]);
                    s = __hadd2(s, (q < 2) ? b_lo : b_hi);
                    s = __hmax2(s, zero2);
                    a_h[q] = *(uint32_t*)&s;
                }
#pragma unroll
                for (int ni = 0; ni < 8; ni++) {
                    int j = ni >> 1, s = ni & 1;
                    mma16816(acc[mi][ni], a_h, b_h[j][s], b_h[j][s + 2]);
                }
            }
        }
    }

    const int tm = lane >> 2;
    const int tn = lane & 3;
#pragma unroll
    for (int mi = 0; mi < 2; mi++) {
#pragma unroll
        for (int h = 0; h < 2; h++) {
            size_t row = m0 + wm * 32 + mi * 16 + h * 8 + tm;
#pragma unroll
            for (int ni = 0; ni < 8; ni++) {
                size_t col = n0 + wn * 64 + ni * 8 + tn * 2;
                float2 bv = *(const float2*)(b4 + col);
                *(float2*)(out + row * 1024 + col) =
                    make_float2(acc[mi][ni][h * 2 + 0] + bv.x,
                                acc[mi][ni][h * 2 + 1] + bv.y);
            }
        }
    }
}

// ---------------------------------------------------------------------------
// Launch: three-stream DAG.
//   s0: W3t -> w2 -> [eWp] -> prep_u -> wait eAct -> U -> wait eV,eW4 -> final
//   s2: zero/mark/scan/act -> [eAct] -> wait eBpV -> V -> [eV]
//   s3: W4t/bias3 -> [eW4] -> wait eWp -> prep_v -> [eBpV]
// ---------------------------------------------------------------------------
extern "C" void kernel_launch(void* const* d_in, const int* in_sizes, int n_in,
                              void* d_out, int out_size) {
    const float* positions = (const float*)d_in[0];
    const int*   parent    = (const int*)d_in[1];
    const float* W1 = (const float*)d_in[2];
    const float* b1 = (const float*)d_in[3];
    const float* W2 = (const float*)d_in[4];
    const float* b2 = (const float*)d_in[5];
    const float* W3 = (const float*)d_in[6];
    const float* b3 = (const float*)d_in[7];
    const float* W4 = (const float*)d_in[8];
    const float* b4 = (const float*)d_in[9];
    float* out = (float*)d_out;

    __half *dAph, *dBp, *dW2h, *dW3th, *dW4th, *dU, *dVc;
    cudaGetSymbolAddress((void**)&dAph, g_Aph);
    cudaGetSymbolAddress((void**)&dBp, g_Bp);
    cudaGetSymbolAddress((void**)&dW2h, g_W2h);
    cudaGetSymbolAddress((void**)&dW3th, g_W3th);
    cudaGetSymbolAddress((void**)&dW4th, g_W4th);
    cudaGetSymbolAddress((void**)&dU, g_U);
    cudaGetSymbolAddress((void**)&dVc, g_Vc);
    float* dbias3;
    cudaGetSymbolAddress((void**)&dbias3, g_bias3);

    cudaFuncSetAttribute(hmma_gemm_kernel<0>,
                         cudaFuncAttributeMaxDynamicSharedMemorySize, DYN_SMEM);
    cudaFuncSetAttribute(hmma_gemm_kernel<2>,
                         cudaFuncAttributeMaxDynamicSharedMemorySize, DYN_SMEM);
    cudaFuncSetAttribute(fused_final_kernel,
                         cudaFuncAttributeMaxDynamicSharedMemorySize, F_DYN);

    // persistent side-streams + events (host handles only; same GPU work each call)
    static cudaStream_t s2 = [] {
        cudaStream_t s;
        cudaStreamCreateWithFlags(&s, cudaStreamNonBlocking);
        return s;
    }();
    static cudaStream_t s3 = [] {
        cudaStream_t s;
        cudaStreamCreateWithFlags(&s, cudaStreamNonBlocking);
        return s;
    }();
    static cudaEvent_t eFork = [] {
        cudaEvent_t e;
        cudaEventCreateWithFlags(&e, cudaEventDisableTiming);
        return e;
    }();
    static cudaEvent_t eAct = [] {
        cudaEvent_t e;
        cudaEventCreateWithFlags(&e, cudaEventDisableTiming);
        return e;
    }();
    static cudaEvent_t eWp = [] {
        cudaEvent_t e;
        cudaEventCreateWithFlags(&e, cudaEventDisableTiming);
        return e;
    }();
    static cudaEvent_t eW4 = [] {
        cudaEvent_t e;
        cudaEventCreateWithFlags(&e, cudaEventDisableTiming);
        return e;
    }();
    static cudaEvent_t eBpV = [] {
        cudaEvent_t e;
        cudaEventCreateWithFlags(&e, cudaEventDisableTiming);
        return e;
    }();
    static cudaEvent_t eV = [] {
        cudaEvent_t e;
        cudaEventCreateWithFlags(&e, cudaEventDisableTiming);
        return e;
    }();

    // fork
    cudaEventRecord(eFork, 0);
    cudaStreamWaitEvent(s2, eFork, 0);
    cudaStreamWaitEvent(s3, eFork, 0);

    // s2: compaction + act
    zero_flags_kernel<<<KTOK / 256, 256, 0, s2>>>();
    mark_kernel<<<KTOK / 256, 256, 0, s2>>>(parent);
    scan_kernel<<<1, 512, 0, s2>>>();
    act_kernel<<<KTOK, 256, 0, s2>>>(positions, W1, b1);
    cudaEventRecord(eAct, s2);

    // s3: W4 transpose + bias3 (final-only prep)
    transpose_hi_kernel<<<dim3(1024 / 32, 2048 / 32), dim3(32, 8), 0, s3>>>(
        W4, dW4th, 2048, 1024);
    bias3_part_kernel<<<dim3(8, 16), 256, 0, s3>>>(W3, b2);
    bias3_reduce_kernel<<<8, 256, 0, s3>>>(b3);
    cudaEventRecord(eW4, s3);

    // s0: W3 transpose + W2 split
    transpose_w3_kernel<<<dim3(2048 / 32, 4096 / 32), dim3(32, 8)>>>(W3);
    split_w2_kernel<<<(512 * 1024) / 256, 256>>>(W2);
    cudaEventRecord(eWp, 0);

    // s0: prep_u (B' rows 0:2048 = W3a^T @ W2^T)
    hmma_gemm_kernel<0><<<dim3(512 / BN, 2048 / BM), NTHREADS, DYN_SMEM>>>(
        dW3th, dW2h, dBp, 1024, 4096, 1024, 1536);

    // s3: prep_v (B' rows 2048:4096 = W3c^T @ W2^T) after eWp
    cudaStreamWaitEvent(s3, eWp, 0);
    hmma_gemm_kernel<0><<<dim3(512 / BN, 2048 / BM), NTHREADS, DYN_SMEM, s3>>>(
        dW3th + 2048, dW2h, dBp + (size_t)2048 * 1536, 1024, 4096, 1024, 1536);
    cudaEventRecord(eBpV, s3);

    // s2: V GEMM (needs B'v + act/scan, both satisfied)
    cudaStreamWaitEvent(s2, eBpV, 0);
    hmma_gemm_kernel<2><<<dim3(2048 / BN, KTOK / BM), NTHREADS, DYN_SMEM, s2>>>(
        dAph, dBp + (size_t)2048 * 1536, dVc, 1536, 1536, 1536, 2048);
    cudaEventRecord(eV, s2);

    // s0: U GEMM (needs act; prep_u precedes on-stream)
    cudaStreamWaitEvent(0, eAct, 0);
    hmma_gemm_kernel<0><<<dim3(2048 / BN, KTOK / BM), NTHREADS, DYN_SMEM>>>(
        dAph, dBp, dU, 1536, 1536, 1536, 2048);

    // s0: fused final (needs U on-stream + Vc + bias3/W4t)
    cudaStreamWaitEvent(0, eV, 0);
    cudaStreamWaitEvent(0, eW4, 0);
    fused_final_kernel<<<dim3(1024 / BN, KTOK / BM), NTHREADS, F_DYN>>>(
        dU, dVc, dW4th, parent, dbias3, b4, out);
}